// round 14
// baseline (speedup 1.0000x reference)
#include <cuda_runtime.h>
#include <cuda_fp16.h>
#include <math.h>
#include <stdint.h>

#define B_ 8
#define N_ 2048
#define D_ 256
#define K_ 512
#define R_ 32
#define NSEG 64      // N_ / 32 column segments for softmax partials

// GEMM tiling: 128x64 tile, 256 threads, 2 CTAs/SM
#define TM 128
#define TN 64
#define BK 64
#define NCHUNKS (D_ / BK)   // 4

// Output packing: scores1 [B,N,N] | soi [B,K*R,3] | rel_e [B,K*R,D], all float32
static constexpr size_t SCORES_ELEMS = (size_t)B_ * N_ * N_;
static constexpr size_t SOI_OFF      = SCORES_ELEMS;
static constexpr size_t RELE_OFF     = SOI_OFF + (size_t)B_ * K_ * R_ * 3;

// Scratch (__device__ globals; no allocation allowed)
__device__ float2 g_part[(size_t)B_ * N_ * NSEG];
__device__ float  g_diag[B_ * N_];
__device__ int    g_inst[B_ * K_];
__device__ __half g_qhi[(size_t)B_ * N_ * D_];
__device__ __half g_qlo[(size_t)B_ * N_ * D_];
__device__ __half g_khi[(size_t)B_ * N_ * D_];
__device__ __half g_klo[(size_t)B_ * N_ * D_];

// ---------------------------------------------------------------------------
// helpers
// ---------------------------------------------------------------------------
__device__ __forceinline__ uint32_t smem_u32(const void* p) {
    uint32_t a;
    asm("{ .reg .u64 t; cvta.to.shared.u64 t, %1; cvt.u32.u64 %0, t; }" : "=r"(a) : "l"(p));
    return a;
}
__device__ __forceinline__ void cpasync16(uint32_t saddr, const void* g) {
    asm volatile("cp.async.ca.shared.global [%0], [%1], 16;" :: "r"(saddr), "l"(g) : "memory");
}
#define CP_COMMIT() asm volatile("cp.async.commit_group;" ::: "memory")
#define CP_WAIT(n)  asm volatile("cp.async.wait_group %0;" :: "n"(n) : "memory")

__device__ __forceinline__ void mma_f16(float* c, const uint32_t* a, const uint32_t* b) {
    asm volatile(
        "mma.sync.aligned.m16n8k16.row.col.f32.f16.f16.f32 "
        "{%0,%1,%2,%3}, {%4,%5,%6,%7}, {%8,%9}, {%0,%1,%2,%3};"
        : "+f"(c[0]), "+f"(c[1]), "+f"(c[2]), "+f"(c[3])
        : "r"(a[0]), "r"(a[1]), "r"(a[2]), "r"(a[3]), "r"(b[0]), "r"(b[1]));
}

// ---------------------------------------------------------------------------
// Kernel 0: split fp32 -> (hi, lo) fp16 pair for q and k
// ---------------------------------------------------------------------------
__global__ __launch_bounds__(256) void decomp_kernel(
    const float* __restrict__ q, const float* __restrict__ k)
{
    const size_t i = (size_t)blockIdx.x * 256 + threadIdx.x;  // float4 index
    {
        float4 x = ((const float4*)q)[i];
        __half h0 = __float2half_rn(x.x), h1 = __float2half_rn(x.y);
        __half h2 = __float2half_rn(x.z), h3 = __float2half_rn(x.w);
        __half l0 = __float2half_rn(x.x - __half2float(h0));
        __half l1 = __float2half_rn(x.y - __half2float(h1));
        __half l2 = __float2half_rn(x.z - __half2float(h2));
        __half l3 = __float2half_rn(x.w - __half2float(h3));
        __half2 hh0 = __halves2half2(h0, h1), hh1 = __halves2half2(h2, h3);
        __half2 ll0 = __halves2half2(l0, l1), ll1 = __halves2half2(l2, l3);
        uint2 ho = make_uint2(*(uint32_t*)&hh0, *(uint32_t*)&hh1);
        uint2 lo = make_uint2(*(uint32_t*)&ll0, *(uint32_t*)&ll1);
        ((uint2*)g_qhi)[i] = ho; ((uint2*)g_qlo)[i] = lo;
    }
    {
        float4 x = ((const float4*)k)[i];
        __half h0 = __float2half_rn(x.x), h1 = __float2half_rn(x.y);
        __half h2 = __float2half_rn(x.z), h3 = __float2half_rn(x.w);
        __half l0 = __float2half_rn(x.x - __half2float(h0));
        __half l1 = __float2half_rn(x.y - __half2float(h1));
        __half l2 = __float2half_rn(x.z - __half2float(h2));
        __half l3 = __float2half_rn(x.w - __half2float(h3));
        __half2 hh0 = __halves2half2(h0, h1), hh1 = __halves2half2(h2, h3);
        __half2 ll0 = __halves2half2(l0, l1), ll1 = __halves2half2(l2, l3);
        uint2 ho = make_uint2(*(uint32_t*)&hh0, *(uint32_t*)&hh1);
        uint2 lo = make_uint2(*(uint32_t*)&ll0, *(uint32_t*)&ll1);
        ((uint2*)g_khi)[i] = ho; ((uint2*)g_klo)[i] = lo;
    }
}

// ---------------------------------------------------------------------------
// Kernel 1: 3xFP16 GEMM via mma.sync (m16n8k16), 128x64 tile, 256 threads,
// 2 CTAs/SM, double-buffered cp.async, pass-outer MMA ordering,
// fused per-32col softmax partials in epilogue.
// ---------------------------------------------------------------------------
static constexpr int S_AHI = 0;          // 128 rows x 128B = 16KB
static constexpr int S_ALO = 16384;      // 16KB
static constexpr int S_BHI = 32768;      // 64 rows x 128B = 8KB
static constexpr int S_BLO = 40960;      // 8KB
static constexpr int STAGE = 49152;      // 48KB
static constexpr int GEMM_SMEM = 2 * STAGE;   // 96KB

__global__ __launch_bounds__(256, 2) void gemm_tc_kernel(float* __restrict__ S)
{
    extern __shared__ char smem[];
    const uint32_t sbase = smem_u32(smem);
    const int tid = threadIdx.x;
    const int wid  = tid >> 5;            // 0..7
    const int lane = tid & 31;
    const int g  = lane >> 2;             // groupID 0..7
    const int tg = lane & 3;              // thread-in-group 0..3
    const int wm = (wid >> 1) * 32;       // warp m base (0,32,64,96)
    const int wn = (wid & 1)  * 32;       // warp n base (0,32)

    const int b  = blockIdx.z;
    const int m0 = blockIdx.y * TM;
    const int n0 = blockIdx.x * TN;

    const uint4* qhi4 = (const uint4*)(g_qhi + (size_t)b * N_ * D_);
    const uint4* qlo4 = (const uint4*)(g_qlo + (size_t)b * N_ * D_);
    const uint4* khi4 = (const uint4*)(g_khi + (size_t)b * N_ * D_);
    const uint4* klo4 = (const uint4*)(g_klo + (size_t)b * N_ * D_);

    const int l_c4 = tid & 7;
    int  rowA[4]; uint32_t swA[4];
#pragma unroll
    for (int t = 0; t < 4; t++) {
        rowA[t] = (t * 256 + tid) >> 3;
        swA[t] = (uint32_t)(rowA[t] * 128 + (l_c4 * 16 ^ ((rowA[t] & 7) << 4)));
    }
    int  rowB[2]; uint32_t swB[2];
#pragma unroll
    for (int t = 0; t < 2; t++) {
        rowB[t] = (t * 256 + tid) >> 3;
        swB[t] = (uint32_t)(rowB[t] * 128 + (l_c4 * 16 ^ ((rowB[t] & 7) << 4)));
    }

    auto load_stage = [&](int c, int buf) {
        const uint32_t sb = sbase + buf * STAGE;
        const int k4 = c * 8;
#pragma unroll
        for (int t = 0; t < 4; t++) {
            size_t gA = (size_t)(m0 + rowA[t]) * 32 + k4 + l_c4;
            cpasync16(sb + S_AHI + swA[t], qhi4 + gA);
            cpasync16(sb + S_ALO + swA[t], qlo4 + gA);
        }
#pragma unroll
        for (int t = 0; t < 2; t++) {
            size_t gB = (size_t)(n0 + rowB[t]) * 32 + k4 + l_c4;
            cpasync16(sb + S_BHI + swB[t], khi4 + gB);
            cpasync16(sb + S_BLO + swB[t], klo4 + gB);
        }
    };

    int ra[2][2], rb[4];
#pragma unroll
    for (int t = 0; t < 2; t++) {
        ra[t][0] = (wm + t * 16 + g) * 128;
        ra[t][1] = (wm + t * 16 + g + 8) * 128;
    }
#pragma unroll
    for (int u = 0; u < 4; u++) rb[u] = (wn + u * 8 + g) * 128;
    const int gx = g << 4;

    float acc[2][4][4];
#pragma unroll
    for (int t = 0; t < 2; t++)
#pragma unroll
        for (int u = 0; u < 4; u++)
#pragma unroll
            for (int r = 0; r < 4; r++) acc[t][u][r] = 0.0f;

    load_stage(0, 0);
    CP_COMMIT();

    for (int c = 0; c < NCHUNKS; c++) {
        if (c + 1 < NCHUNKS) { load_stage(c + 1, (c + 1) & 1); CP_COMMIT(); CP_WAIT(1); }
        else                 { CP_WAIT(0); }
        __syncthreads();

        const char* sb = smem + (c & 1) * STAGE;
#pragma unroll
        for (int ks = 0; ks < 4; ks++) {
            const int kb  = ks * 32 + tg * 4;
            const int kx0 = kb ^ gx;
            const int kx1 = (kb + 16) ^ gx;

            uint32_t ahi[2][4], alo[2][4], bhi[4][2], blo[4][2];
#pragma unroll
            for (int t = 0; t < 2; t++) {
                ahi[t][0] = *(const uint32_t*)(sb + S_AHI + ra[t][0] + kx0);
                ahi[t][1] = *(const uint32_t*)(sb + S_AHI + ra[t][1] + kx0);
                ahi[t][2] = *(const uint32_t*)(sb + S_AHI + ra[t][0] + kx1);
                ahi[t][3] = *(const uint32_t*)(sb + S_AHI + ra[t][1] + kx1);
                alo[t][0] = *(const uint32_t*)(sb + S_ALO + ra[t][0] + kx0);
                alo[t][1] = *(const uint32_t*)(sb + S_ALO + ra[t][1] + kx0);
                alo[t][2] = *(const uint32_t*)(sb + S_ALO + ra[t][0] + kx1);
                alo[t][3] = *(const uint32_t*)(sb + S_ALO + ra[t][1] + kx1);
            }
#pragma unroll
            for (int u = 0; u < 4; u++) {
                bhi[u][0] = *(const uint32_t*)(sb + S_BHI + rb[u] + kx0);
                bhi[u][1] = *(const uint32_t*)(sb + S_BHI + rb[u] + kx1);
                blo[u][0] = *(const uint32_t*)(sb + S_BLO + rb[u] + kx0);
                blo[u][1] = *(const uint32_t*)(sb + S_BLO + rb[u] + kx1);
            }
#pragma unroll
            for (int t = 0; t < 2; t++)
#pragma unroll
                for (int u = 0; u < 4; u++)
                    mma_f16(acc[t][u], ahi[t], bhi[u]);
#pragma unroll
            for (int t = 0; t < 2; t++)
#pragma unroll
                for (int u = 0; u < 4; u++)
                    mma_f16(acc[t][u], ahi[t], blo[u]);
#pragma unroll
            for (int t = 0; t < 2; t++)
#pragma unroll
                for (int u = 0; u < 4; u++)
                    mma_f16(acc[t][u], alo[t], bhi[u]);
        }
        __syncthreads();
    }

    const int seg = (n0 >> 5) + (wid & 1);
#pragma unroll
    for (int t = 0; t < 2; t++) {
#pragma unroll
        for (int h = 0; h < 2; h++) {
            const int row = m0 + wm + t * 16 + g + h * 8;
            float* Sr = S + ((size_t)b * N_ + row) * N_ + n0 + wn;
            float mx = -INFINITY;
#pragma unroll
            for (int u = 0; u < 4; u++) {
                float v0 = acc[t][u][h * 2], v1 = acc[t][u][h * 2 + 1];
                *(float2*)(Sr + u * 8 + tg * 2) = make_float2(v0, v1);
                mx = fmaxf(mx, fmaxf(v0, v1));
            }
            mx = fmaxf(mx, __shfl_xor_sync(0xffffffffu, mx, 1));
            mx = fmaxf(mx, __shfl_xor_sync(0xffffffffu, mx, 2));
            float sm = 0.0f;
#pragma unroll
            for (int u = 0; u < 4; u++)
                sm += expf(acc[t][u][h * 2] - mx) + expf(acc[t][u][h * 2 + 1] - mx);
            sm += __shfl_xor_sync(0xffffffffu, sm, 1);
            sm += __shfl_xor_sync(0xffffffffu, sm, 2);
            if (tg == 0)
                g_part[((size_t)b * N_ + row) * NSEG + seg] = make_float2(mx, sm);
        }
    }
}

// ---------------------------------------------------------------------------
// Kernel 2: combine per-seg partials -> diagonal softmax prob per row
// ---------------------------------------------------------------------------
__global__ __launch_bounds__(256) void combine_kernel(const float* __restrict__ S)
{
    const int row  = blockIdx.x * 8 + (threadIdx.x >> 5);
    const int lane = threadIdx.x & 31;
    const float2* p = g_part + (size_t)row * NSEG;
    float2 p0 = p[lane], p1 = p[lane + 32];
    float m = fmaxf(p0.x, p1.x);
#pragma unroll
    for (int o = 16; o > 0; o >>= 1) m = fmaxf(m, __shfl_xor_sync(0xffffffffu, m, o));
    float Z = p0.y * expf(p0.x - m) + p1.y * expf(p1.x - m);
#pragma unroll
    for (int o = 16; o > 0; o >>= 1) Z += __shfl_xor_sync(0xffffffffu, Z, o);
    if (lane == 0) {
        const int i = row & (N_ - 1);
        g_diag[row] = expf(S[(size_t)row * N_ + i] - m) / Z;
    }
}

// ---------------------------------------------------------------------------
// Kernel 3: fused top-512 via 32-way PARALLEL binary search + stable
// compaction (vectorized count loop, REDUX reduce).
// ---------------------------------------------------------------------------
__global__ __launch_bounds__(1024) void topk_kernel()
{
    __shared__ uint32_t bits[N_];
    __shared__ int cnt[32];
    __shared__ uint32_t sLo, sHi;
    __shared__ int wsum[32];
    __shared__ int s_total;

    const int b = blockIdx.x;
    const int t = threadIdx.x;
    const int wid = t >> 5, lane = t & 31;

    const float* src = g_diag + b * N_;
    bits[t]        = __float_as_uint(src[t]);
    bits[t + 1024] = __float_as_uint(src[t + 1024]);
    __syncthreads();

    const uint4* bits4 = (const uint4*)bits;
    uint32_t lo = 0, hi = 0x3F800000u;   // diag in (0,1] -> pred(hi) true
    while (lo < hi) {
        const uint32_t span = hi - lo;
        const uint32_t m = lo + (uint32_t)(((unsigned long long)span * (wid + 1)) / 33);
        int c = 0;
#pragma unroll
        for (int i = 0; i < N_ / 128; i++) {
            uint4 v = bits4[i * 32 + lane];
            c += (v.x > m) + (v.y > m) + (v.z > m) + (v.w > m);
        }
        c = __reduce_add_sync(0xffffffffu, c);
        if (lane == 0) cnt[wid] = c;
        __syncthreads();
        if (wid == 0) {
            const uint32_t mw = lo + (uint32_t)(((unsigned long long)span * (lane + 1)) / 33);
            const int cw = cnt[lane];
            uint32_t nlo = (cw >= K_) ? (mw + 1) : lo;
            uint32_t nhi = (cw <  K_) ? mw       : hi;
#pragma unroll
            for (int o = 16; o > 0; o >>= 1) {
                nlo = max(nlo, __shfl_xor_sync(0xffffffffu, nlo, o));
                nhi = min(nhi, __shfl_xor_sync(0xffffffffu, nhi, o));
            }
            if (lane == 0) { sLo = nlo; sHi = nhi; }
        }
        __syncthreads();
        lo = sLo; hi = sHi;
    }
    const uint32_t T = lo;

    const uint32_t b0 = bits[2 * t], b1 = bits[2 * t + 1];
    const int f0 = b0 > T,  f1 = b1 > T;
    const int e0 = b0 == T, e1 = b1 == T;
    const int val = ((f0 + f1) << 16) | (e0 + e1);

    int inc = val;
#pragma unroll
    for (int o = 1; o < 32; o <<= 1) {
        int up = __shfl_up_sync(0xffffffffu, inc, o);
        if (lane >= o) inc += up;
    }
    if (lane == 31) wsum[wid] = inc;
    __syncthreads();

    if (wid == 0) {
        int s = wsum[lane];
        int si = s;
#pragma unroll
        for (int o = 1; o < 32; o <<= 1) {
            int up = __shfl_up_sync(0xffffffffu, si, o);
            if (lane >= o) si += up;
        }
        wsum[lane] = si - s;
        if (lane == 31) s_total = si;
    }
    __syncthreads();

    const int incl = inc + wsum[wid];
    const int total_gt = s_total >> 16;
    const int need_eq = K_ - total_gt;
    const int excl_f = (incl >> 16) - (f0 + f1);
    const int excl_e = (incl & 0xFFFF) - (e0 + e1);

    const bool sel0 = f0 || (e0 && excl_e < need_eq);
    const bool sel1 = f1 || (e1 && (excl_e + e0) < need_eq);
    const int pos0 = excl_f + min(excl_e, need_eq);
    const int pos1 = excl_f + f0 + min(excl_e + e0, need_eq);
    if (sel0) g_inst[b * K_ + pos0] = 2 * t;
    if (sel1) g_inst[b * K_ + pos1] = 2 * t + 1;
}

// ---------------------------------------------------------------------------
// Kernel 4 (FUSED select+emit): one block per (b,a), 256 threads.
// Warp 0: register-resident threshold top-32 (gather 512 vals into 16 regs,
// binary-search 32nd-largest threshold with REDUX, ballot-compact ascending)
// -> s_obj + soi. Then all 8 warps emit 4 layernormed relations each.
// Selection predicate identical to prior rounds: top-32 by (value desc,
// index asc), diagonal forced to max.
// ---------------------------------------------------------------------------
__global__ __launch_bounds__(256) void selemit_kernel(
    const float* __restrict__ S, const float* __restrict__ Q,
    float* __restrict__ out)
{
    const int blk  = blockIdx.x;
    const int b    = blk >> 9;
    const int a    = blk & (K_ - 1);
    const int wid  = threadIdx.x >> 5;
    const int lane = threadIdx.x & 31;
    const uint32_t ltmask = (1u << lane) - 1u;

    __shared__ int s_inst[K_];
    __shared__ int s_obj[R_];

    for (int c = threadIdx.x; c < K_; c += 256) s_inst[c] = g_inst[b * K_ + c];
    __syncthreads();

    const int ia = s_inst[a];
    // all warps preload subject row while warp 0 selects
    const float4* qa4 = (const float4*)(Q + ((size_t)b * N_ + ia) * D_) + lane * 2;
    const float4 a0 = qa4[0], a1 = qa4[1];

    const size_t base = (size_t)b * K_ + a;

    if (wid == 0) {
        const float* Srow = S + ((size_t)b * N_ + ia) * N_;

        // gather + monotone map: u = bits>=0 ? bits|0x80000000 : ~bits
        uint32_t u[16];
#pragma unroll
        for (int r = 0; r < 16; r++) {
            const int c = r * 32 + lane;
            const uint32_t bb = __float_as_uint(Srow[s_inst[c]]);
            uint32_t m = (bb & 0x80000000u) ? ~bb : (bb | 0x80000000u);
            if (c == a) m = 0xFFFFFFFFu;   // diagonal forced to max
            u[r] = m;
        }

        // binary search: T = smallest m with count(u > m) < 32
        uint32_t lo = 0, hi = 0xFFFFFFFFu;
        while (lo < hi) {
            const uint32_t mid = lo + ((hi - lo) >> 1);
            int c = 0;
#pragma unroll
            for (int r = 0; r < 16; r++) c += (u[r] > mid);
            c = __reduce_add_sync(0xffffffffu, c);
            if (c >= R_) lo = mid + 1; else hi = mid;
        }
        const uint32_t T = lo;

        int cg = 0;
#pragma unroll
        for (int r = 0; r < 16; r++) cg += (u[r] > T);
        const int total_gt = __reduce_add_sync(0xffffffffu, cg);
        const int need_eq = R_ - total_gt;

        // stable compaction in ascending index order
        float* soi = out + SOI_OFF + base * R_ * 3;
        int run_sel = 0, run_eq = 0;
#pragma unroll
        for (int r = 0; r < 16; r++) {
            const bool gt = u[r] > T;
            const bool eq = u[r] == T;
            const uint32_t meq = __ballot_sync(0xffffffffu, eq);
            const int eq_rank = run_eq + __popc(meq & ltmask);
            const bool sel = gt || (eq && eq_rank < need_eq);
            const uint32_t msel = __ballot_sync(0xffffffffu, sel);
            if (sel) {
                const int slot = run_sel + __popc(msel & ltmask);
                const int obj = s_inst[r * 32 + lane];
                s_obj[slot] = obj;
                soi[slot * 3 + 0] = (float)b;
                soi[slot * 3 + 1] = (float)ia;
                soi[slot * 3 + 2] = (float)obj;
            }
            run_eq  += __popc(meq);
            run_sel += __popc(msel);
        }
    }
    __syncthreads();

    // emit: 8 warps x 4 relations
#pragma unroll
    for (int it = 0; it < 4; it++) {
        const int r = wid * 4 + it;
        const int obj = s_obj[r];
        const float4* qo = (const float4*)(Q + ((size_t)b * N_ + obj) * D_) + lane * 2;
        float4 x0 = qo[0], x1 = qo[1];
        x0.x += a0.x; x0.y += a0.y; x0.z += a0.z; x0.w += a0.w;
        x1.x += a1.x; x1.y += a1.y; x1.z += a1.z; x1.w += a1.w;

        float s = x0.x + x0.y + x0.z + x0.w + x1.x + x1.y + x1.z + x1.w;
#pragma unroll
        for (int o = 16; o > 0; o >>= 1) s += __shfl_xor_sync(0xffffffffu, s, o);
        const float mu = s * (1.0f / 256.0f);

        float d0x = x0.x - mu, d0y = x0.y - mu, d0z = x0.z - mu, d0w = x0.w - mu;
        float d1x = x1.x - mu, d1y = x1.y - mu, d1z = x1.z - mu, d1w = x1.w - mu;
        float s2 = d0x*d0x + d0y*d0y + d0z*d0z + d0w*d0w
                 + d1x*d1x + d1y*d1y + d1z*d1z + d1w*d1w;
#pragma unroll
        for (int o = 16; o > 0; o >>= 1) s2 += __shfl_xor_sync(0xffffffffu, s2, o);
        const float rn = rsqrtf(s2 * (1.0f / 256.0f) + 1e-5f);

        float4* o4 = (float4*)(out + RELE_OFF + (base * R_ + r) * D_) + lane * 2;
        o4[0] = make_float4(d0x * rn, d0y * rn, d0z * rn, d0w * rn);
        o4[1] = make_float4(d1x * rn, d1y * rn, d1z * rn, d1w * rn);
    }
}

// ---------------------------------------------------------------------------
extern "C" void kernel_launch(void* const* d_in, const int* in_sizes, int n_in,
                              void* d_out, int out_size)
{
    const float* q = (const float*)d_in[0];
    const float* k = (const float*)d_in[1];
    float* out = (float*)d_out;
    float* S = out;

    cudaFuncSetAttribute(gemm_tc_kernel,
                         cudaFuncAttributeMaxDynamicSharedMemorySize, GEMM_SMEM);

    decomp_kernel<<<(B_ * N_ * D_ / 4) / 256, 256>>>(q, k);

    dim3 gGemm(N_ / TN, N_ / TM, B_);
    gemm_tc_kernel<<<gGemm, 256, GEMM_SMEM>>>(S);

    combine_kernel<<<B_ * N_ / 8, 256>>>(S);

    topk_kernel<<<B_, 1024>>>();

    selemit_kernel<<<B_ * K_, 256>>>(S, q, out);
}

// round 15
// speedup vs baseline: 1.0305x; 1.0305x over previous
#include <cuda_runtime.h>
#include <cuda_fp16.h>
#include <math.h>
#include <stdint.h>

#define B_ 8
#define N_ 2048
#define D_ 256
#define K_ 512
#define R_ 32
#define NSEG 64      // N_ / 32 column segments for softmax partials

// GEMM tiling: 128x64 tile, 256 threads
#define TM 128
#define TN 64
#define BK 64
#define NCHUNKS (D_ / BK)   // 4

// Output packing: scores1 [B,N,N] | soi [B,K*R,3] | rel_e [B,K*R,D], all float32
static constexpr size_t SCORES_ELEMS = (size_t)B_ * N_ * N_;
static constexpr size_t SOI_OFF      = SCORES_ELEMS;
static constexpr size_t RELE_OFF     = SOI_OFF + (size_t)B_ * K_ * R_ * 3;

// Scratch (__device__ globals; no allocation allowed)
__device__ float2 g_part[(size_t)B_ * N_ * NSEG];
__device__ float  g_diag[B_ * N_];
__device__ int    g_inst[B_ * K_];
__device__ int    g_obj [B_ * K_ * R_];

// ---------------------------------------------------------------------------
// helpers
// ---------------------------------------------------------------------------
__device__ __forceinline__ void mma_f16(float* c, const uint32_t* a, const uint32_t* b) {
    asm volatile(
        "mma.sync.aligned.m16n8k16.row.col.f32.f16.f16.f32 "
        "{%0,%1,%2,%3}, {%4,%5,%6,%7}, {%8,%9}, {%0,%1,%2,%3};"
        : "+f"(c[0]), "+f"(c[1]), "+f"(c[2]), "+f"(c[3])
        : "r"(a[0]), "r"(a[1]), "r"(a[2]), "r"(a[3]), "r"(b[0]), "r"(b[1]));
}

// fp32x8 -> hi fp16x8 (uint4) + lo fp16x8 (uint4); identical math to the old
// decomp kernel: h = rn(x), l = rn(x - h).
__device__ __forceinline__ void cvt_pair(const float4 a, const float4 b,
                                         uint4& hi, uint4& lo) {
    __half h0 = __float2half_rn(a.x), h1 = __float2half_rn(a.y);
    __half h2 = __float2half_rn(a.z), h3 = __float2half_rn(a.w);
    __half h4 = __float2half_rn(b.x), h5 = __float2half_rn(b.y);
    __half h6 = __float2half_rn(b.z), h7 = __float2half_rn(b.w);
    __half l0 = __float2half_rn(a.x - __half2float(h0));
    __half l1 = __float2half_rn(a.y - __half2float(h1));
    __half l2 = __float2half_rn(a.z - __half2float(h2));
    __half l3 = __float2half_rn(a.w - __half2float(h3));
    __half l4 = __float2half_rn(b.x - __half2float(h4));
    __half l5 = __float2half_rn(b.y - __half2float(h5));
    __half l6 = __float2half_rn(b.z - __half2float(h6));
    __half l7 = __float2half_rn(b.w - __half2float(h7));
    __half2 p;
    p = __halves2half2(h0, h1); hi.x = *(uint32_t*)&p;
    p = __halves2half2(h2, h3); hi.y = *(uint32_t*)&p;
    p = __halves2half2(h4, h5); hi.z = *(uint32_t*)&p;
    p = __halves2half2(h6, h7); hi.w = *(uint32_t*)&p;
    p = __halves2half2(l0, l1); lo.x = *(uint32_t*)&p;
    p = __halves2half2(l2, l3); lo.y = *(uint32_t*)&p;
    p = __halves2half2(l4, l5); lo.z = *(uint32_t*)&p;
    p = __halves2half2(l6, l7); lo.w = *(uint32_t*)&p;
}

// ---------------------------------------------------------------------------
// Kernel 1: 3xFP16 GEMM via mma.sync (m16n8k16), 128x64 tile, 256 threads.
// Reads raw fp32 q/k (same bytes as hi+lo fp16), converts to hi/lo in
// registers, STS into swizzled smem tiles. Prefetch LDGs for chunk c+1 issue
// before chunk c's MMA loop; convert+STS after. Fused softmax partials.
// ---------------------------------------------------------------------------
static constexpr int S_AHI = 0;          // 128 rows x 128B = 16KB
static constexpr int S_ALO = 16384;      // 16KB
static constexpr int S_BHI = 32768;      // 64 rows x 128B = 8KB
static constexpr int S_BLO = 40960;      // 8KB
static constexpr int STAGE = 49152;      // 48KB
static constexpr int GEMM_SMEM = 2 * STAGE;   // 96KB

__global__ __launch_bounds__(256) void gemm_tc_kernel(
    const float* __restrict__ Q, const float* __restrict__ Km, float* __restrict__ S)
{
    extern __shared__ char smem[];
    const int tid = threadIdx.x;
    const int wid  = tid >> 5;            // 0..7
    const int lane = tid & 31;
    const int g  = lane >> 2;             // groupID 0..7
    const int tg = lane & 3;              // thread-in-group 0..3
    const int wm = (wid >> 1) * 32;       // warp m base (0,32,64,96)
    const int wn = (wid & 1)  * 32;       // warp n base (0,32)

    const int b  = blockIdx.z;
    const int m0 = blockIdx.y * TM;
    const int n0 = blockIdx.x * TN;

    const float4* qf4 = (const float4*)(Q  + (size_t)b * N_ * D_);  // 64 f4/row
    const float4* kf4 = (const float4*)(Km + (size_t)b * N_ * D_);

    // loader mapping: A tile = 128 rows x 8 16B-units (4 units/thread),
    // B tile = 64 rows x 8 units (2 units/thread). (t*256+tid)&7 == tid&7.
    const int l_c4 = tid & 7;
    int  rowA[4]; uint32_t swA[4];
#pragma unroll
    for (int t = 0; t < 4; t++) {
        rowA[t] = (t * 256 + tid) >> 3;
        swA[t] = (uint32_t)(rowA[t] * 128 + (l_c4 * 16 ^ ((rowA[t] & 7) << 4)));
    }
    int  rowB[2]; uint32_t swB[2];
#pragma unroll
    for (int t = 0; t < 2; t++) {
        rowB[t] = (t * 256 + tid) >> 3;
        swB[t] = (uint32_t)(rowB[t] * 128 + (l_c4 * 16 ^ ((rowB[t] & 7) << 4)));
    }

    float4 pfA[4][2], pfB[2][2];   // prefetch registers (fp32)

    auto load_regs = [&](int c) {
        const int kf = c * 16 + l_c4 * 2;   // float4 index within row
#pragma unroll
        for (int t = 0; t < 4; t++) {
            size_t gA = (size_t)(m0 + rowA[t]) * 64 + kf;
            pfA[t][0] = qf4[gA]; pfA[t][1] = qf4[gA + 1];
        }
#pragma unroll
        for (int t = 0; t < 2; t++) {
            size_t gB = (size_t)(n0 + rowB[t]) * 64 + kf;
            pfB[t][0] = kf4[gB]; pfB[t][1] = kf4[gB + 1];
        }
    };

    auto store_stage = [&](int buf) {
        char* sb = smem + buf * STAGE;
#pragma unroll
        for (int t = 0; t < 4; t++) {
            uint4 hi, lo;
            cvt_pair(pfA[t][0], pfA[t][1], hi, lo);
            *(uint4*)(sb + S_AHI + swA[t]) = hi;
            *(uint4*)(sb + S_ALO + swA[t]) = lo;
        }
#pragma unroll
        for (int t = 0; t < 2; t++) {
            uint4 hi, lo;
            cvt_pair(pfB[t][0], pfB[t][1], hi, lo);
            *(uint4*)(sb + S_BHI + swB[t]) = hi;
            *(uint4*)(sb + S_BLO + swB[t]) = lo;
        }
    };

    // fragment row byte offsets
    int ra[2][2], rb[4];
#pragma unroll
    for (int t = 0; t < 2; t++) {
        ra[t][0] = (wm + t * 16 + g) * 128;
        ra[t][1] = (wm + t * 16 + g + 8) * 128;
    }
#pragma unroll
    for (int u = 0; u < 4; u++) rb[u] = (wn + u * 8 + g) * 128;
    const int gx = g << 4;

    float acc[2][4][4];
#pragma unroll
    for (int t = 0; t < 2; t++)
#pragma unroll
        for (int u = 0; u < 4; u++)
#pragma unroll
            for (int r = 0; r < 4; r++) acc[t][u][r] = 0.0f;

    load_regs(0);
    store_stage(0);
    __syncthreads();

    for (int c = 0; c < NCHUNKS; c++) {
        if (c + 1 < NCHUNKS) load_regs(c + 1);   // issue LDGs; MMA hides latency

        const char* sb = smem + (c & 1) * STAGE;
#pragma unroll
        for (int ks = 0; ks < 4; ks++) {
            const int kb  = ks * 32 + tg * 4;
            const int kx0 = kb ^ gx;
            const int kx1 = (kb + 16) ^ gx;

            uint32_t ahi[2][4], alo[2][4], bhi[4][2], blo[4][2];
#pragma unroll
            for (int t = 0; t < 2; t++) {
                ahi[t][0] = *(const uint32_t*)(sb + S_AHI + ra[t][0] + kx0);
                ahi[t][1] = *(const uint32_t*)(sb + S_AHI + ra[t][1] + kx0);
                ahi[t][2] = *(const uint32_t*)(sb + S_AHI + ra[t][0] + kx1);
                ahi[t][3] = *(const uint32_t*)(sb + S_AHI + ra[t][1] + kx1);
                alo[t][0] = *(const uint32_t*)(sb + S_ALO + ra[t][0] + kx0);
                alo[t][1] = *(const uint32_t*)(sb + S_ALO + ra[t][1] + kx0);
                alo[t][2] = *(const uint32_t*)(sb + S_ALO + ra[t][0] + kx1);
                alo[t][3] = *(const uint32_t*)(sb + S_ALO + ra[t][1] + kx1);
            }
#pragma unroll
            for (int u = 0; u < 4; u++) {
                bhi[u][0] = *(const uint32_t*)(sb + S_BHI + rb[u] + kx0);
                bhi[u][1] = *(const uint32_t*)(sb + S_BHI + rb[u] + kx1);
                blo[u][0] = *(const uint32_t*)(sb + S_BLO + rb[u] + kx0);
                blo[u][1] = *(const uint32_t*)(sb + S_BLO + rb[u] + kx1);
            }
            // pass-outer ordering: RAW distance 8 on each accumulator
#pragma unroll
            for (int t = 0; t < 2; t++)
#pragma unroll
                for (int u = 0; u < 4; u++)
                    mma_f16(acc[t][u], ahi[t], bhi[u]);
#pragma unroll
            for (int t = 0; t < 2; t++)
#pragma unroll
                for (int u = 0; u < 4; u++)
                    mma_f16(acc[t][u], ahi[t], blo[u]);
#pragma unroll
            for (int t = 0; t < 2; t++)
#pragma unroll
                for (int u = 0; u < 4; u++)
                    mma_f16(acc[t][u], alo[t], bhi[u]);
        }

        if (c + 1 < NCHUNKS) store_stage((c + 1) & 1);  // writes other buffer
        __syncthreads();
    }

    // Epilogue: store S + per (row, 32-col segment) softmax partials
    const int seg = (n0 >> 5) + (wid & 1);
#pragma unroll
    for (int t = 0; t < 2; t++) {
#pragma unroll
        for (int h = 0; h < 2; h++) {
            const int row = m0 + wm + t * 16 + g + h * 8;
            float* Sr = S + ((size_t)b * N_ + row) * N_ + n0 + wn;
            float mx = -INFINITY;
#pragma unroll
            for (int u = 0; u < 4; u++) {
                float v0 = acc[t][u][h * 2], v1 = acc[t][u][h * 2 + 1];
                *(float2*)(Sr + u * 8 + tg * 2) = make_float2(v0, v1);
                mx = fmaxf(mx, fmaxf(v0, v1));
            }
            mx = fmaxf(mx, __shfl_xor_sync(0xffffffffu, mx, 1));
            mx = fmaxf(mx, __shfl_xor_sync(0xffffffffu, mx, 2));
            float sm = 0.0f;
#pragma unroll
            for (int u = 0; u < 4; u++)
                sm += expf(acc[t][u][h * 2] - mx) + expf(acc[t][u][h * 2 + 1] - mx);
            sm += __shfl_xor_sync(0xffffffffu, sm, 1);
            sm += __shfl_xor_sync(0xffffffffu, sm, 2);
            if (tg == 0)
                g_part[((size_t)b * N_ + row) * NSEG + seg] = make_float2(mx, sm);
        }
    }
}

// ---------------------------------------------------------------------------
// Kernel 2: combine per-seg partials -> diagonal softmax prob per row
// ---------------------------------------------------------------------------
__global__ __launch_bounds__(256) void combine_kernel(const float* __restrict__ S)
{
    const int row  = blockIdx.x * 8 + (threadIdx.x >> 5);
    const int lane = threadIdx.x & 31;
    const float2* p = g_part + (size_t)row * NSEG;
    float2 p0 = p[lane], p1 = p[lane + 32];
    float m = fmaxf(p0.x, p1.x);
#pragma unroll
    for (int o = 16; o > 0; o >>= 1) m = fmaxf(m, __shfl_xor_sync(0xffffffffu, m, o));
    float Z = p0.y * expf(p0.x - m) + p1.y * expf(p1.x - m);
#pragma unroll
    for (int o = 16; o > 0; o >>= 1) Z += __shfl_xor_sync(0xffffffffu, Z, o);
    if (lane == 0) {
        const int i = row & (N_ - 1);
        g_diag[row] = expf(S[(size_t)row * N_ + i] - m) / Z;
    }
}

// ---------------------------------------------------------------------------
// Kernel 3: fused top-512 via 32-way PARALLEL binary search + stable
// compaction (vectorized count loop, REDUX reduce).
// ---------------------------------------------------------------------------
__global__ __launch_bounds__(1024) void topk_kernel()
{
    __shared__ uint32_t bits[N_];
    __shared__ int cnt[32];
    __shared__ uint32_t sLo, sHi;
    __shared__ int wsum[32];
    __shared__ int s_total;

    const int b = blockIdx.x;
    const int t = threadIdx.x;
    const int wid = t >> 5, lane = t & 31;

    const float* src = g_diag + b * N_;
    bits[t]        = __float_as_uint(src[t]);
    bits[t + 1024] = __float_as_uint(src[t + 1024]);
    __syncthreads();

    const uint4* bits4 = (const uint4*)bits;
    uint32_t lo = 0, hi = 0x3F800000u;   // diag in (0,1] -> pred(hi) true
    while (lo < hi) {
        const uint32_t span = hi - lo;
        const uint32_t m = lo + (uint32_t)(((unsigned long long)span * (wid + 1)) / 33);
        int c = 0;
#pragma unroll
        for (int i = 0; i < N_ / 128; i++) {
            uint4 v = bits4[i * 32 + lane];
            c += (v.x > m) + (v.y > m) + (v.z > m) + (v.w > m);
        }
        c = __reduce_add_sync(0xffffffffu, c);
        if (lane == 0) cnt[wid] = c;
        __syncthreads();
        if (wid == 0) {
            const uint32_t mw = lo + (uint32_t)(((unsigned long long)span * (lane + 1)) / 33);
            const int cw = cnt[lane];
            uint32_t nlo = (cw >= K_) ? (mw + 1) : lo;
            uint32_t nhi = (cw <  K_) ? mw       : hi;
#pragma unroll
            for (int o = 16; o > 0; o >>= 1) {
                nlo = max(nlo, __shfl_xor_sync(0xffffffffu, nlo, o));
                nhi = min(nhi, __shfl_xor_sync(0xffffffffu, nhi, o));
            }
            if (lane == 0) { sLo = nlo; sHi = nhi; }
        }
        __syncthreads();
        lo = sLo; hi = sHi;
    }
    const uint32_t T = lo;

    const uint32_t b0 = bits[2 * t], b1 = bits[2 * t + 1];
    const int f0 = b0 > T,  f1 = b1 > T;
    const int e0 = b0 == T, e1 = b1 == T;
    const int val = ((f0 + f1) << 16) | (e0 + e1);

    int inc = val;
#pragma unroll
    for (int o = 1; o < 32; o <<= 1) {
        int up = __shfl_up_sync(0xffffffffu, inc, o);
        if (lane >= o) inc += up;
    }
    if (lane == 31) wsum[wid] = inc;
    __syncthreads();

    if (wid == 0) {
        int s = wsum[lane];
        int si = s;
#pragma unroll
        for (int o = 1; o < 32; o <<= 1) {
            int up = __shfl_up_sync(0xffffffffu, si, o);
            if (lane >= o) si += up;
        }
        wsum[lane] = si - s;
        if (lane == 31) s_total = si;
    }
    __syncthreads();

    const int incl = inc + wsum[wid];
    const int total_gt = s_total >> 16;
    const int need_eq = K_ - total_gt;
    const int excl_f = (incl >> 16) - (f0 + f1);
    const int excl_e = (incl & 0xFFFF) - (e0 + e1);

    const bool sel0 = f0 || (e0 && excl_e < need_eq);
    const bool sel1 = f1 || (e1 && (excl_e + e0) < need_eq);
    const int pos0 = excl_f + min(excl_e, need_eq);
    const int pos1 = excl_f + f0 + min(excl_e + e0, need_eq);
    if (sel0) g_inst[b * K_ + pos0] = 2 * t;
    if (sel1) g_inst[b * K_ + pos1] = 2 * t + 1;
}

// ---------------------------------------------------------------------------
// Kernel 4: register-resident threshold top-32 per (b,a) (round-13 version:
// 8 warps per block each own one row — full parallel select).
// ---------------------------------------------------------------------------
__global__ __launch_bounds__(256) void select_kernel(
    const float* __restrict__ S, float* __restrict__ out)
{
    const int warp = threadIdx.x >> 5;
    const int lane = threadIdx.x & 31;
    const int b = blockIdx.x >> 6;
    const int a = ((blockIdx.x & 63) << 3) + warp;
    const uint32_t ltmask = (1u << lane) - 1u;

    __shared__ int s_inst[K_];
    for (int c = threadIdx.x; c < K_; c += 256) s_inst[c] = g_inst[b * K_ + c];
    __syncthreads();

    const int ia = s_inst[a];
    const float* Srow = S + ((size_t)b * N_ + ia) * N_;

    // gather + monotone map: u = bits>=0 ? bits|0x80000000 : ~bits
    uint32_t u[16];
#pragma unroll
    for (int r = 0; r < 16; r++) {
        const int c = r * 32 + lane;
        const uint32_t bb = __float_as_uint(Srow[s_inst[c]]);
        uint32_t m = (bb & 0x80000000u) ? ~bb : (bb | 0x80000000u);
        if (c == a) m = 0xFFFFFFFFu;   // diagonal forced to max
        u[r] = m;
    }

    // binary search: T = smallest m with count(u > m) < 32
    uint32_t lo = 0, hi = 0xFFFFFFFFu;
    while (lo < hi) {
        const uint32_t mid = lo + ((hi - lo) >> 1);
        int c = 0;
#pragma unroll
        for (int r = 0; r < 16; r++) c += (u[r] > mid);
        c = __reduce_add_sync(0xffffffffu, c);
        if (c >= R_) lo = mid + 1; else hi = mid;
    }
    const uint32_t T = lo;

    int cg = 0;
#pragma unroll
    for (int r = 0; r < 16; r++) cg += (u[r] > T);
    const int total_gt = __reduce_add_sync(0xffffffffu, cg);
    const int need_eq = R_ - total_gt;

    // stable compaction in ascending index order
    const size_t base = (size_t)b * K_ + a;
    float* soi = out + SOI_OFF + base * R_ * 3;
    int run_sel = 0, run_eq = 0;
#pragma unroll
    for (int r = 0; r < 16; r++) {
        const bool gt = u[r] > T;
        const bool eq = u[r] == T;
        const uint32_t meq = __ballot_sync(0xffffffffu, eq);
        const int eq_rank = run_eq + __popc(meq & ltmask);
        const bool sel = gt || (eq && eq_rank < need_eq);
        const uint32_t msel = __ballot_sync(0xffffffffu, sel);
        if (sel) {
            const int slot = run_sel + __popc(msel & ltmask);
            const int obj = s_inst[r * 32 + lane];
            g_obj[base * R_ + slot] = obj;
            soi[slot * 3 + 0] = (float)b;
            soi[slot * 3 + 1] = (float)ia;
            soi[slot * 3 + 2] = (float)obj;
        }
        run_eq  += __popc(meq);
        run_sel += __popc(msel);
    }
}

// ---------------------------------------------------------------------------
// Kernel 5: emit rel_e. One block per (b,a); 8 warps x 4 relations each.
// ---------------------------------------------------------------------------
__global__ __launch_bounds__(256) void emit_kernel(
    const float* __restrict__ Q, float* __restrict__ out)
{
    const int blk  = blockIdx.x;
    const int b    = blk >> 9;
    const int a    = blk & (K_ - 1);
    const int wid  = threadIdx.x >> 5;
    const int lane = threadIdx.x & 31;

    const int ia = g_inst[b * K_ + a];
    const float4* qa4 = (const float4*)(Q + ((size_t)b * N_ + ia) * D_) + lane * 2;
    const float4 a0 = qa4[0], a1 = qa4[1];

    const size_t base = (size_t)b * K_ + a;

#pragma unroll
    for (int it = 0; it < 4; it++) {
        const int r = wid * 4 + it;
        const int obj = g_obj[base * R_ + r];
        const float4* qo = (const float4*)(Q + ((size_t)b * N_ + obj) * D_) + lane * 2;
        float4 x0 = qo[0], x1 = qo[1];
        x0.x += a0.x; x0.y += a0.y; x0.z += a0.z; x0.w += a0.w;
        x1.x += a1.x; x1.y += a1.y; x1.z += a1.z; x1.w += a1.w;

        float s = x0.x + x0.y + x0.z + x0.w + x1.x + x1.y + x1.z + x1.w;
#pragma unroll
        for (int o = 16; o > 0; o >>= 1) s += __shfl_xor_sync(0xffffffffu, s, o);
        const float mu = s * (1.0f / 256.0f);

        float d0x = x0.x - mu, d0y = x0.y - mu, d0z = x0.z - mu, d0w = x0.w - mu;
        float d1x = x1.x - mu, d1y = x1.y - mu, d1z = x1.z - mu, d1w = x1.w - mu;
        float s2 = d0x*d0x + d0y*d0y + d0z*d0z + d0w*d0w
                 + d1x*d1x + d1y*d1y + d1z*d1z + d1w*d1w;
#pragma unroll
        for (int o = 16; o > 0; o >>= 1) s2 += __shfl_xor_sync(0xffffffffu, s2, o);
        const float rn = rsqrtf(s2 * (1.0f / 256.0f) + 1e-5f);

        float4* o4 = (float4*)(out + RELE_OFF + (base * R_ + r) * D_) + lane * 2;
        o4[0] = make_float4(d0x * rn, d0y * rn, d0z * rn, d0w * rn);
        o4[1] = make_float4(d1x * rn, d1y * rn, d1z * rn, d1w * rn);
    }
}

// ---------------------------------------------------------------------------
extern "C" void kernel_launch(void* const* d_in, const int* in_sizes, int n_in,
                              void* d_out, int out_size)
{
    const float* q = (const float*)d_in[0];
    const float* k = (const float*)d_in[1];
    float* out = (float*)d_out;
    float* S = out;

    cudaFuncSetAttribute(gemm_tc_kernel,
                         cudaFuncAttributeMaxDynamicSharedMemorySize, GEMM_SMEM);

    dim3 gGemm(N_ / TN, N_ / TM, B_);
    gemm_tc_kernel<<<gGemm, 256, GEMM_SMEM>>>(q, k, S);

    combine_kernel<<<B_ * N_ / 8, 256>>>(S);

    topk_kernel<<<B_, 1024>>>();

    select_kernel<<<B_ * K_ / 8, 256>>>(S, out);

    emit_kernel<<<B_ * K_, 256>>>(q, out);
}

// round 16
// speedup vs baseline: 1.1365x; 1.1029x over previous
#include <cuda_runtime.h>
#include <cuda_fp16.h>
#include <math.h>
#include <stdint.h>

#define B_ 8
#define N_ 2048
#define D_ 256
#define K_ 512
#define R_ 32
#define NSEG 64      // N_ / 32 column segments for softmax partials

// GEMM tiling: 128x64 tile, 256 threads, 2 CTAs/SM
#define TM 128
#define TN 64
#define BK 64
#define NCHUNKS (D_ / BK)   // 4

// Output packing: scores1 [B,N,N] | soi [B,K*R,3] | rel_e [B,K*R,D], all float32
static constexpr size_t SCORES_ELEMS = (size_t)B_ * N_ * N_;
static constexpr size_t SOI_OFF      = SCORES_ELEMS;
static constexpr size_t RELE_OFF     = SOI_OFF + (size_t)B_ * K_ * R_ * 3;

// Scratch (__device__ globals; no allocation allowed)
__device__ float2 g_part[(size_t)B_ * N_ * NSEG];
__device__ float  g_diag[B_ * N_];
__device__ int    g_inst[B_ * K_];
__device__ __half g_qhi[(size_t)B_ * N_ * D_];
__device__ __half g_qlo[(size_t)B_ * N_ * D_];
__device__ __half g_khi[(size_t)B_ * N_ * D_];
__device__ __half g_klo[(size_t)B_ * N_ * D_];

// ---------------------------------------------------------------------------
// helpers
// ---------------------------------------------------------------------------
__device__ __forceinline__ uint32_t smem_u32(const void* p) {
    uint32_t a;
    asm("{ .reg .u64 t; cvta.to.shared.u64 t, %1; cvt.u32.u64 %0, t; }" : "=r"(a) : "l"(p));
    return a;
}
__device__ __forceinline__ void cpasync16(uint32_t saddr, const void* g) {
    asm volatile("cp.async.ca.shared.global [%0], [%1], 16;" :: "r"(saddr), "l"(g) : "memory");
}
#define CP_COMMIT() asm volatile("cp.async.commit_group;" ::: "memory")
#define CP_WAIT(n)  asm volatile("cp.async.wait_group %0;" :: "n"(n) : "memory")

__device__ __forceinline__ void mma_f16(float* c, const uint32_t* a, const uint32_t* b) {
    asm volatile(
        "mma.sync.aligned.m16n8k16.row.col.f32.f16.f16.f32 "
        "{%0,%1,%2,%3}, {%4,%5,%6,%7}, {%8,%9}, {%0,%1,%2,%3};"
        : "+f"(c[0]), "+f"(c[1]), "+f"(c[2]), "+f"(c[3])
        : "r"(a[0]), "r"(a[1]), "r"(a[2]), "r"(a[3]), "r"(b[0]), "r"(b[1]));
}

// ---------------------------------------------------------------------------
// Kernel 0: split fp32 -> (hi, lo) fp16 pair for q and k
// ---------------------------------------------------------------------------
__global__ __launch_bounds__(256) void decomp_kernel(
    const float* __restrict__ q, const float* __restrict__ k)
{
    const size_t i = (size_t)blockIdx.x * 256 + threadIdx.x;  // float4 index
    {
        float4 x = ((const float4*)q)[i];
        __half h0 = __float2half_rn(x.x), h1 = __float2half_rn(x.y);
        __half h2 = __float2half_rn(x.z), h3 = __float2half_rn(x.w);
        __half l0 = __float2half_rn(x.x - __half2float(h0));
        __half l1 = __float2half_rn(x.y - __half2float(h1));
        __half l2 = __float2half_rn(x.z - __half2float(h2));
        __half l3 = __float2half_rn(x.w - __half2float(h3));
        __half2 hh0 = __halves2half2(h0, h1), hh1 = __halves2half2(h2, h3);
        __half2 ll0 = __halves2half2(l0, l1), ll1 = __halves2half2(l2, l3);
        uint2 ho = make_uint2(*(uint32_t*)&hh0, *(uint32_t*)&hh1);
        uint2 lo = make_uint2(*(uint32_t*)&ll0, *(uint32_t*)&ll1);
        ((uint2*)g_qhi)[i] = ho; ((uint2*)g_qlo)[i] = lo;
    }
    {
        float4 x = ((const float4*)k)[i];
        __half h0 = __float2half_rn(x.x), h1 = __float2half_rn(x.y);
        __half h2 = __float2half_rn(x.z), h3 = __float2half_rn(x.w);
        __half l0 = __float2half_rn(x.x - __half2float(h0));
        __half l1 = __float2half_rn(x.y - __half2float(h1));
        __half l2 = __float2half_rn(x.z - __half2float(h2));
        __half l3 = __float2half_rn(x.w - __half2float(h3));
        __half2 hh0 = __halves2half2(h0, h1), hh1 = __halves2half2(h2, h3);
        __half2 ll0 = __halves2half2(l0, l1), ll1 = __halves2half2(l2, l3);
        uint2 ho = make_uint2(*(uint32_t*)&hh0, *(uint32_t*)&hh1);
        uint2 lo = make_uint2(*(uint32_t*)&ll0, *(uint32_t*)&ll1);
        ((uint2*)g_khi)[i] = ho; ((uint2*)g_klo)[i] = lo;
    }
}

// ---------------------------------------------------------------------------
// Kernel 1: 3xFP16 GEMM via mma.sync (m16n8k16), 128x64 tile, 256 threads,
// 2 CTAs/SM, double-buffered cp.async, pass-outer MMA ordering,
// fused per-32col softmax partials in epilogue.  (round-13 version)
// ---------------------------------------------------------------------------
static constexpr int S_AHI = 0;          // 128 rows x 128B = 16KB
static constexpr int S_ALO = 16384;      // 16KB
static constexpr int S_BHI = 32768;      // 64 rows x 128B = 8KB
static constexpr int S_BLO = 40960;      // 8KB
static constexpr int STAGE = 49152;      // 48KB
static constexpr int GEMM_SMEM = 2 * STAGE;   // 96KB

__global__ __launch_bounds__(256, 2) void gemm_tc_kernel(float* __restrict__ S)
{
    extern __shared__ char smem[];
    const uint32_t sbase = smem_u32(smem);
    const int tid = threadIdx.x;
    const int wid  = tid >> 5;            // 0..7
    const int lane = tid & 31;
    const int g  = lane >> 2;             // groupID 0..7
    const int tg = lane & 3;              // thread-in-group 0..3
    const int wm = (wid >> 1) * 32;       // warp m base (0,32,64,96)
    const int wn = (wid & 1)  * 32;       // warp n base (0,32)

    const int b  = blockIdx.z;
    const int m0 = blockIdx.y * TM;
    const int n0 = blockIdx.x * TN;

    const uint4* qhi4 = (const uint4*)(g_qhi + (size_t)b * N_ * D_);
    const uint4* qlo4 = (const uint4*)(g_qlo + (size_t)b * N_ * D_);
    const uint4* khi4 = (const uint4*)(g_khi + (size_t)b * N_ * D_);
    const uint4* klo4 = (const uint4*)(g_klo + (size_t)b * N_ * D_);

    const int l_c4 = tid & 7;
    int  rowA[4]; uint32_t swA[4];
#pragma unroll
    for (int t = 0; t < 4; t++) {
        rowA[t] = (t * 256 + tid) >> 3;
        swA[t] = (uint32_t)(rowA[t] * 128 + (l_c4 * 16 ^ ((rowA[t] & 7) << 4)));
    }
    int  rowB[2]; uint32_t swB[2];
#pragma unroll
    for (int t = 0; t < 2; t++) {
        rowB[t] = (t * 256 + tid) >> 3;
        swB[t] = (uint32_t)(rowB[t] * 128 + (l_c4 * 16 ^ ((rowB[t] & 7) << 4)));
    }

    auto load_stage = [&](int c, int buf) {
        const uint32_t sb = sbase + buf * STAGE;
        const int k4 = c * 8;
#pragma unroll
        for (int t = 0; t < 4; t++) {
            size_t gA = (size_t)(m0 + rowA[t]) * 32 + k4 + l_c4;
            cpasync16(sb + S_AHI + swA[t], qhi4 + gA);
            cpasync16(sb + S_ALO + swA[t], qlo4 + gA);
        }
#pragma unroll
        for (int t = 0; t < 2; t++) {
            size_t gB = (size_t)(n0 + rowB[t]) * 32 + k4 + l_c4;
            cpasync16(sb + S_BHI + swB[t], khi4 + gB);
            cpasync16(sb + S_BLO + swB[t], klo4 + gB);
        }
    };

    int ra[2][2], rb[4];
#pragma unroll
    for (int t = 0; t < 2; t++) {
        ra[t][0] = (wm + t * 16 + g) * 128;
        ra[t][1] = (wm + t * 16 + g + 8) * 128;
    }
#pragma unroll
    for (int u = 0; u < 4; u++) rb[u] = (wn + u * 8 + g) * 128;
    const int gx = g << 4;

    float acc[2][4][4];
#pragma unroll
    for (int t = 0; t < 2; t++)
#pragma unroll
        for (int u = 0; u < 4; u++)
#pragma unroll
            for (int r = 0; r < 4; r++) acc[t][u][r] = 0.0f;

    load_stage(0, 0);
    CP_COMMIT();

    for (int c = 0; c < NCHUNKS; c++) {
        if (c + 1 < NCHUNKS) { load_stage(c + 1, (c + 1) & 1); CP_COMMIT(); CP_WAIT(1); }
        else                 { CP_WAIT(0); }
        __syncthreads();

        const char* sb = smem + (c & 1) * STAGE;
#pragma unroll
        for (int ks = 0; ks < 4; ks++) {
            const int kb  = ks * 32 + tg * 4;
            const int kx0 = kb ^ gx;
            const int kx1 = (kb + 16) ^ gx;

            uint32_t ahi[2][4], alo[2][4], bhi[4][2], blo[4][2];
#pragma unroll
            for (int t = 0; t < 2; t++) {
                ahi[t][0] = *(const uint32_t*)(sb + S_AHI + ra[t][0] + kx0);
                ahi[t][1] = *(const uint32_t*)(sb + S_AHI + ra[t][1] + kx0);
                ahi[t][2] = *(const uint32_t*)(sb + S_AHI + ra[t][0] + kx1);
                ahi[t][3] = *(const uint32_t*)(sb + S_AHI + ra[t][1] + kx1);
                alo[t][0] = *(const uint32_t*)(sb + S_ALO + ra[t][0] + kx0);
                alo[t][1] = *(const uint32_t*)(sb + S_ALO + ra[t][1] + kx0);
                alo[t][2] = *(const uint32_t*)(sb + S_ALO + ra[t][0] + kx1);
                alo[t][3] = *(const uint32_t*)(sb + S_ALO + ra[t][1] + kx1);
            }
#pragma unroll
            for (int u = 0; u < 4; u++) {
                bhi[u][0] = *(const uint32_t*)(sb + S_BHI + rb[u] + kx0);
                bhi[u][1] = *(const uint32_t*)(sb + S_BHI + rb[u] + kx1);
                blo[u][0] = *(const uint32_t*)(sb + S_BLO + rb[u] + kx0);
                blo[u][1] = *(const uint32_t*)(sb + S_BLO + rb[u] + kx1);
            }
#pragma unroll
            for (int t = 0; t < 2; t++)
#pragma unroll
                for (int u = 0; u < 4; u++)
                    mma_f16(acc[t][u], ahi[t], bhi[u]);
#pragma unroll
            for (int t = 0; t < 2; t++)
#pragma unroll
                for (int u = 0; u < 4; u++)
                    mma_f16(acc[t][u], ahi[t], blo[u]);
#pragma unroll
            for (int t = 0; t < 2; t++)
#pragma unroll
                for (int u = 0; u < 4; u++)
                    mma_f16(acc[t][u], alo[t], bhi[u]);
        }
        __syncthreads();
    }

    const int seg = (n0 >> 5) + (wid & 1);
#pragma unroll
    for (int t = 0; t < 2; t++) {
#pragma unroll
        for (int h = 0; h < 2; h++) {
            const int row = m0 + wm + t * 16 + g + h * 8;
            float* Sr = S + ((size_t)b * N_ + row) * N_ + n0 + wn;
            float mx = -INFINITY;
#pragma unroll
            for (int u = 0; u < 4; u++) {
                float v0 = acc[t][u][h * 2], v1 = acc[t][u][h * 2 + 1];
                *(float2*)(Sr + u * 8 + tg * 2) = make_float2(v0, v1);
                mx = fmaxf(mx, fmaxf(v0, v1));
            }
            mx = fmaxf(mx, __shfl_xor_sync(0xffffffffu, mx, 1));
            mx = fmaxf(mx, __shfl_xor_sync(0xffffffffu, mx, 2));
            float sm = 0.0f;
#pragma unroll
            for (int u = 0; u < 4; u++)
                sm += expf(acc[t][u][h * 2] - mx) + expf(acc[t][u][h * 2 + 1] - mx);
            sm += __shfl_xor_sync(0xffffffffu, sm, 1);
            sm += __shfl_xor_sync(0xffffffffu, sm, 2);
            if (tg == 0)
                g_part[((size_t)b * N_ + row) * NSEG + seg] = make_float2(mx, sm);
        }
    }
}

// ---------------------------------------------------------------------------
// Kernel 2: combine per-seg partials -> diagonal softmax prob per row
// ---------------------------------------------------------------------------
__global__ __launch_bounds__(256) void combine_kernel(const float* __restrict__ S)
{
    const int row  = blockIdx.x * 8 + (threadIdx.x >> 5);
    const int lane = threadIdx.x & 31;
    const float2* p = g_part + (size_t)row * NSEG;
    float2 p0 = p[lane], p1 = p[lane + 32];
    float m = fmaxf(p0.x, p1.x);
#pragma unroll
    for (int o = 16; o > 0; o >>= 1) m = fmaxf(m, __shfl_xor_sync(0xffffffffu, m, o));
    float Z = p0.y * expf(p0.x - m) + p1.y * expf(p1.x - m);
#pragma unroll
    for (int o = 16; o > 0; o >>= 1) Z += __shfl_xor_sync(0xffffffffu, Z, o);
    if (lane == 0) {
        const int i = row & (N_ - 1);
        g_diag[row] = expf(S[(size_t)row * N_ + i] - m) / Z;
    }
}

// ---------------------------------------------------------------------------
// Kernel 3: fused top-512 via 32-way PARALLEL binary search + stable
// compaction (vectorized count loop, REDUX reduce).
// ---------------------------------------------------------------------------
__global__ __launch_bounds__(1024) void topk_kernel()
{
    __shared__ uint32_t bits[N_];
    __shared__ int cnt[32];
    __shared__ uint32_t sLo, sHi;
    __shared__ int wsum[32];
    __shared__ int s_total;

    const int b = blockIdx.x;
    const int t = threadIdx.x;
    const int wid = t >> 5, lane = t & 31;

    const float* src = g_diag + b * N_;
    bits[t]        = __float_as_uint(src[t]);
    bits[t + 1024] = __float_as_uint(src[t + 1024]);
    __syncthreads();

    const uint4* bits4 = (const uint4*)bits;
    uint32_t lo = 0, hi = 0x3F800000u;   // diag in (0,1] -> pred(hi) true
    while (lo < hi) {
        const uint32_t span = hi - lo;
        const uint32_t m = lo + (uint32_t)(((unsigned long long)span * (wid + 1)) / 33);
        int c = 0;
#pragma unroll
        for (int i = 0; i < N_ / 128; i++) {
            uint4 v = bits4[i * 32 + lane];
            c += (v.x > m) + (v.y > m) + (v.z > m) + (v.w > m);
        }
        c = __reduce_add_sync(0xffffffffu, c);
        if (lane == 0) cnt[wid] = c;
        __syncthreads();
        if (wid == 0) {
            const uint32_t mw = lo + (uint32_t)(((unsigned long long)span * (lane + 1)) / 33);
            const int cw = cnt[lane];
            uint32_t nlo = (cw >= K_) ? (mw + 1) : lo;
            uint32_t nhi = (cw <  K_) ? mw       : hi;
#pragma unroll
            for (int o = 16; o > 0; o >>= 1) {
                nlo = max(nlo, __shfl_xor_sync(0xffffffffu, nlo, o));
                nhi = min(nhi, __shfl_xor_sync(0xffffffffu, nhi, o));
            }
            if (lane == 0) { sLo = nlo; sHi = nhi; }
        }
        __syncthreads();
        lo = sLo; hi = sHi;
    }
    const uint32_t T = lo;

    const uint32_t b0 = bits[2 * t], b1 = bits[2 * t + 1];
    const int f0 = b0 > T,  f1 = b1 > T;
    const int e0 = b0 == T, e1 = b1 == T;
    const int val = ((f0 + f1) << 16) | (e0 + e1);

    int inc = val;
#pragma unroll
    for (int o = 1; o < 32; o <<= 1) {
        int up = __shfl_up_sync(0xffffffffu, inc, o);
        if (lane >= o) inc += up;
    }
    if (lane == 31) wsum[wid] = inc;
    __syncthreads();

    if (wid == 0) {
        int s = wsum[lane];
        int si = s;
#pragma unroll
        for (int o = 1; o < 32; o <<= 1) {
            int up = __shfl_up_sync(0xffffffffu, si, o);
            if (lane >= o) si += up;
        }
        wsum[lane] = si - s;
        if (lane == 31) s_total = si;
    }
    __syncthreads();

    const int incl = inc + wsum[wid];
    const int total_gt = s_total >> 16;
    const int need_eq = K_ - total_gt;
    const int excl_f = (incl >> 16) - (f0 + f1);
    const int excl_e = (incl & 0xFFFF) - (e0 + e1);

    const bool sel0 = f0 || (e0 && excl_e < need_eq);
    const bool sel1 = f1 || (e1 && (excl_e + e0) < need_eq);
    const int pos0 = excl_f + min(excl_e, need_eq);
    const int pos1 = excl_f + f0 + min(excl_e + e0, need_eq);
    if (sel0) g_inst[b * K_ + pos0] = 2 * t;
    if (sel1) g_inst[b * K_ + pos1] = 2 * t + 1;
}

// ---------------------------------------------------------------------------
// Kernel 4 (merged select+emit, WARP-PARALLEL): 512 blocks x 8 warps;
// each warp owns one (b,a) row: register-threshold top-32 select (identical
// predicate: value desc, index asc, diagonal forced max), soi store, then the
// same warp streams its 32 layernormed relations. No cross-warp dependency.
// ---------------------------------------------------------------------------
__global__ __launch_bounds__(256) void selemit_kernel(
    const float* __restrict__ S, const float* __restrict__ Q,
    float* __restrict__ out)
{
    const int warp = threadIdx.x >> 5;
    const int lane = threadIdx.x & 31;
    const int b = blockIdx.x >> 6;
    const int a = ((blockIdx.x & 63) << 3) + warp;
    const uint32_t ltmask = (1u << lane) - 1u;

    __shared__ int s_inst[K_];
    __shared__ int s_obj[8][R_];

    for (int c = threadIdx.x; c < K_; c += 256) s_inst[c] = g_inst[b * K_ + c];
    __syncthreads();

    const int ia = s_inst[a];
    const float* Srow = S + ((size_t)b * N_ + ia) * N_;

    // gather + monotone map: u = bits>=0 ? bits|0x80000000 : ~bits
    uint32_t u[16];
#pragma unroll
    for (int r = 0; r < 16; r++) {
        const int c = r * 32 + lane;
        const uint32_t bb = __float_as_uint(Srow[s_inst[c]]);
        uint32_t m = (bb & 0x80000000u) ? ~bb : (bb | 0x80000000u);
        if (c == a) m = 0xFFFFFFFFu;   // diagonal forced to max
        u[r] = m;
    }

    // binary search: T = smallest m with count(u > m) < 32
    uint32_t lo = 0, hi = 0xFFFFFFFFu;
    while (lo < hi) {
        const uint32_t mid = lo + ((hi - lo) >> 1);
        int c = 0;
#pragma unroll
        for (int r = 0; r < 16; r++) c += (u[r] > mid);
        c = __reduce_add_sync(0xffffffffu, c);
        if (c >= R_) lo = mid + 1; else hi = mid;
    }
    const uint32_t T = lo;

    int cg = 0;
#pragma unroll
    for (int r = 0; r < 16; r++) cg += (u[r] > T);
    const int total_gt = __reduce_add_sync(0xffffffffu, cg);
    const int need_eq = R_ - total_gt;

    // stable compaction in ascending index order -> s_obj + soi
    const size_t base = (size_t)b * K_ + a;
    float* soi = out + SOI_OFF + base * R_ * 3;
    int run_sel = 0, run_eq = 0;
#pragma unroll
    for (int r = 0; r < 16; r++) {
        const bool gt = u[r] > T;
        const bool eq = u[r] == T;
        const uint32_t meq = __ballot_sync(0xffffffffu, eq);
        const int eq_rank = run_eq + __popc(meq & ltmask);
        const bool sel = gt || (eq && eq_rank < need_eq);
        const uint32_t msel = __ballot_sync(0xffffffffu, sel);
        if (sel) {
            const int slot = run_sel + __popc(msel & ltmask);
            const int obj = s_inst[r * 32 + lane];
            s_obj[warp][slot] = obj;
            soi[slot * 3 + 0] = (float)b;
            soi[slot * 3 + 1] = (float)ia;
            soi[slot * 3 + 2] = (float)obj;
        }
        run_eq  += __popc(meq);
        run_sel += __popc(msel);
    }
    __syncwarp();

    // emit: this warp streams its 32 relations
    const float4* qa4 = (const float4*)(Q + ((size_t)b * N_ + ia) * D_) + lane * 2;
    const float4 a0 = qa4[0], a1 = qa4[1];

    for (int r = 0; r < R_; r++) {
        const int obj = s_obj[warp][r];
        const float4* qo = (const float4*)(Q + ((size_t)b * N_ + obj) * D_) + lane * 2;
        float4 x0 = qo[0], x1 = qo[1];
        x0.x += a0.x; x0.y += a0.y; x0.z += a0.z; x0.w += a0.w;
        x1.x += a1.x; x1.y += a1.y; x1.z += a1.z; x1.w += a1.w;

        float s = x0.x + x0.y + x0.z + x0.w + x1.x + x1.y + x1.z + x1.w;
#pragma unroll
        for (int o = 16; o > 0; o >>= 1) s += __shfl_xor_sync(0xffffffffu, s, o);
        const float mu = s * (1.0f / 256.0f);

        float d0x = x0.x - mu, d0y = x0.y - mu, d0z = x0.z - mu, d0w = x0.w - mu;
        float d1x = x1.x - mu, d1y = x1.y - mu, d1z = x1.z - mu, d1w = x1.w - mu;
        float s2 = d0x*d0x + d0y*d0y + d0z*d0z + d0w*d0w
                 + d1x*d1x + d1y*d1y + d1z*d1z + d1w*d1w;
#pragma unroll
        for (int o = 16; o > 0; o >>= 1) s2 += __shfl_xor_sync(0xffffffffu, s2, o);
        const float rn = rsqrtf(s2 * (1.0f / 256.0f) + 1e-5f);

        float4* o4 = (float4*)(out + RELE_OFF + (base * R_ + r) * D_) + lane * 2;
        o4[0] = make_float4(d0x * rn, d0y * rn, d0z * rn, d0w * rn);
        o4[1] = make_float4(d1x * rn, d1y * rn, d1z * rn, d1w * rn);
    }
}

// ---------------------------------------------------------------------------
extern "C" void kernel_launch(void* const* d_in, const int* in_sizes, int n_in,
                              void* d_out, int out_size)
{
    const float* q = (const float*)d_in[0];
    const float* k = (const float*)d_in[1];
    float* out = (float*)d_out;
    float* S = out;

    cudaFuncSetAttribute(gemm_tc_kernel,
                         cudaFuncAttributeMaxDynamicSharedMemorySize, GEMM_SMEM);

    decomp_kernel<<<(B_ * N_ * D_ / 4) / 256, 256>>>(q, k);

    dim3 gGemm(N_ / TN, N_ / TM, B_);
    gemm_tc_kernel<<<gGemm, 256, GEMM_SMEM>>>(S);

    combine_kernel<<<B_ * N_ / 8, 256>>>(S);

    topk_kernel<<<B_, 1024>>>();

    selemit_kernel<<<B_ * K_ / 8, 256>>>(S, q, out);
}